// round 7
// baseline (speedup 1.0000x reference)
#include <cuda_runtime.h>
#include <math.h>
#include <stdint.h>

#define NND 384
#define DIMC 256
#define EDGC 128
#define NHEAD 8
#define DH 64
#define INNERC 512
#define FFC 1024
#define NN (NND*NND)

#define BM 128
#define BN 64
#define BKP 20   // padded smem row (floats): conflict-free (g,ctg) fragment loads

// ---------------- device scratch ----------------
__device__ float g_x[NND*DIMC];
__device__ float g_h[NND*DIMC];
__device__ float g_q[NND*INNERC];
__device__ float g_kv[NND*2*INNERC];
__device__ float g_vT[INNERC*NND];
__device__ float g_u[NND*NHEAD*EDGC];
__device__ float g_sim[NHEAD*NN];
__device__ float g_w[NND*NHEAD*EDGC];
__device__ float g_attout[NND*INNERC];
__device__ float g_proj[NND*DIMC];
__device__ float g_ff[NND*FFC];
__device__ float g_part[786432];
__device__ float g_wT[2228224];

#define WT_Q   0
#define WT_KV  131072
#define WT_E   393216
#define WT_O   458752
#define WT_1   589824
#define WT_2   851968
#define WT_LSTR 1114112

// ---------------- tf32 helpers ----------------
__device__ __forceinline__ uint32_t f2tf32(float f){
  uint32_t r; asm("cvt.rna.tf32.f32 %0, %1;" : "=r"(r) : "f"(f)); return r;
}
__device__ __forceinline__ void mma_tf32(float c[4], uint32_t a0, uint32_t a1,
    uint32_t a2, uint32_t a3, uint32_t b0, uint32_t b1){
  asm volatile("mma.sync.aligned.m16n8k8.row.col.f32.tf32.tf32.f32 "
    "{%0,%1,%2,%3}, {%4,%5,%6,%7}, {%8,%9}, {%0,%1,%2,%3};"
    : "+f"(c[0]),"+f"(c[1]),"+f"(c[2]),"+f"(c[3])
    : "r"(a0),"r"(a1),"r"(a2),"r"(a3),"r"(b0),"r"(b1));
}
__device__ __forceinline__ void store_hl(uint32_t* sh, uint32_t* sl, int idx, float4 v){
  uint32_t hx=f2tf32(v.x), hy=f2tf32(v.y), hz=f2tf32(v.z), hw=f2tf32(v.w);
  uint4 h; h.x=hx; h.y=hy; h.z=hz; h.w=hw;
  uint4 l;
  l.x = f2tf32(v.x - __uint_as_float(hx));
  l.y = f2tf32(v.y - __uint_as_float(hy));
  l.z = f2tf32(v.z - __uint_as_float(hz));
  l.w = f2tf32(v.w - __uint_as_float(hw));
  *(uint4*)&sh[idx] = h;
  *(uint4*)&sl[idx] = l;
}

// ---------------- tensor-core GEMM ----------------
// A [.., K] k-major (lda), B [N, K] k-major (ldb). M fixed = 384, tiles BM=128 (grid.y=3).
// MODE 0: C[z] = alpha*(A[z]@B[z]^T) + bias[z]   (z batches via sA/sB/sC/sBias)
// MODE 2: z = bat*nsplit+sp; partial over K-chunk (K param = kper) -> part + z*384*N
template<int MODE>
__global__ __launch_bounds__(256) void gemm_tc(
    int N, int K, int nsplit,
    const float* __restrict__ A, int lda, long long sA,
    const float* __restrict__ B, int ldb, long long sB,
    float* __restrict__ C, int ldc, long long sC,
    const float* __restrict__ bias, long long sBias, float alpha)
{
  __shared__ uint32_t sAh[BM*BKP], sAl[BM*BKP], sBh[BN*BKP], sBl[BN*BKP];
  int tid = threadIdx.x;
  int z = blockIdx.z;
  if (MODE == 2){
    int bat = z / nsplit, sp = z - bat*nsplit;
    A += (long long)bat*sA + (long long)sp*K;
    B += (long long)bat*sB + (long long)sp*K;
    C += (long long)z * (384LL * N);
    ldc = N;
  } else {
    A += (long long)z*sA; B += (long long)z*sB; C += (long long)z*sC;
    if (bias) bias += (long long)z*sBias;
  }
  int bm = blockIdx.y*BM, bn = blockIdx.x*BN;
  int r = tid>>2, c4 = (tid&3)<<2;
  const float* Ag0 = A + (long long)(bm + r)*lda + c4;
  const float* Ag1 = A + (long long)(bm + r + 64)*lda + c4;
  const float* Bg  = B + (long long)(bn + r)*ldb + c4;
  int stsA0 = r*BKP + c4;
  int stsA1 = (r+64)*BKP + c4;
  int stsB  = r*BKP + c4;

  int wid = tid>>5, lane = tid&31;
  int wm = (wid&3)*32, wn = (wid>>2)*32;
  int g = lane>>2, ctg = lane&3;

  float acc[2][4][4];
  #pragma unroll
  for (int i=0;i<2;i++)
    #pragma unroll
    for (int j=0;j<4;j++)
      #pragma unroll
      for (int k=0;k<4;k++) acc[i][j][k]=0.f;

  int S = K >> 4;
  float4 pa0 = *(const float4*)Ag0;
  float4 pa1 = *(const float4*)Ag1;
  float4 pb  = *(const float4*)Bg;

  for (int s = 0; s < S; s++){
    __syncthreads();
    store_hl(sAh, sAl, stsA0, pa0);
    store_hl(sAh, sAl, stsA1, pa1);
    store_hl(sBh, sBl, stsB,  pb);
    __syncthreads();
    if (s+1 < S){
      int k = (s+1)<<4;
      pa0 = *(const float4*)(Ag0 + k);
      pa1 = *(const float4*)(Ag1 + k);
      pb  = *(const float4*)(Bg + k);
    }
    #pragma unroll
    for (int kk = 0; kk < 2; kk++){
      int kb = kk*8 + ctg;
      uint32_t ah[2][4], al[2][4], bh[4][2], bl[4][2];
      #pragma unroll
      for (int tm=0; tm<2; tm++){
        int a0 = (wm + tm*16 + g)*BKP + kb;
        ah[tm][0]=sAh[a0];           al[tm][0]=sAl[a0];
        ah[tm][1]=sAh[a0+8*BKP];     al[tm][1]=sAl[a0+8*BKP];
        ah[tm][2]=sAh[a0+4];         al[tm][2]=sAl[a0+4];
        ah[tm][3]=sAh[a0+8*BKP+4];   al[tm][3]=sAl[a0+8*BKP+4];
      }
      #pragma unroll
      for (int tn=0; tn<4; tn++){
        int b0 = (wn + tn*8 + g)*BKP + kb;
        bh[tn][0]=sBh[b0];   bl[tn][0]=sBl[b0];
        bh[tn][1]=sBh[b0+4]; bl[tn][1]=sBl[b0+4];
      }
      #pragma unroll
      for (int tm=0; tm<2; tm++)
        #pragma unroll
        for (int tn=0; tn<4; tn++){
          mma_tf32(acc[tm][tn], ah[tm][0],ah[tm][1],ah[tm][2],ah[tm][3], bh[tn][0],bh[tn][1]);
          mma_tf32(acc[tm][tn], ah[tm][0],ah[tm][1],ah[tm][2],ah[tm][3], bl[tn][0],bl[tn][1]);
          mma_tf32(acc[tm][tn], al[tm][0],al[tm][1],al[tm][2],al[tm][3], bh[tn][0],bh[tn][1]);
        }
    }
  }

  #pragma unroll
  for (int tm=0;tm<2;tm++){
    int r0 = bm + wm + tm*16 + g;
    #pragma unroll
    for (int tn=0;tn<4;tn++){
      int n0 = bn + wn + tn*8 + ctg*2;
      float bx=0.f, by=0.f;
      if (MODE==0 && bias){ float2 bb = *(const float2*)(bias + n0); bx=bb.x; by=bb.y; }
      float a = (MODE==0) ? alpha : 1.f;
      float2 v0 = make_float2(acc[tm][tn][0]*a + bx, acc[tm][tn][1]*a + by);
      float2 v1 = make_float2(acc[tm][tn][2]*a + bx, acc[tm][tn][3]*a + by);
      *(float2*)(C + (long long)r0*ldc + n0) = v0;
      *(float2*)(C + (long long)(r0+8)*ldc + n0) = v1;
    }
  }
}

// ---------------- split-K epilogue reduce ----------------
template<bool GELU, bool ACCUM>
__global__ __launch_bounds__(256) void reduce_k(
    const float* __restrict__ part, int nsplit, int M, int N,
    float* __restrict__ C, int ldc, long long sC,
    const float* __restrict__ bias, long long sBias, int batch)
{
  int idx = blockIdx.x * 256 + threadIdx.x;
  int per = (M*N) >> 2;
  if (idx >= batch * per) return;
  int b = idx / per;
  int r = idx - b*per;
  int n4c = N >> 2;
  int m = r / n4c;
  int n = (r - m*n4c) << 2;
  long long mn = (long long)M * N;
  const float* p = part + (long long)b*nsplit*mn + (long long)m*N + n;
  float4 s = make_float4(0.f,0.f,0.f,0.f);
  for (int sp = 0; sp < nsplit; sp++){
    float4 v = *(const float4*)(p + (long long)sp*mn);
    s.x += v.x; s.y += v.y; s.z += v.z; s.w += v.w;
  }
  if (bias){
    const float* bb = bias + (long long)b*sBias + n;
    s.x += bb[0]; s.y += bb[1]; s.z += bb[2]; s.w += bb[3];
  }
  float* o = C + (long long)b*sC + (long long)m*ldc + n;
  if (ACCUM){
    float4 c = *(const float4*)o;
    s.x += c.x; s.y += c.y; s.z += c.z; s.w += c.w;
  }
  if (GELU){
    s.x *= normcdff(s.x); s.y *= normcdff(s.y);
    s.z *= normcdff(s.z); s.w *= normcdff(s.w);
  }
  *(float4*)o = s;
}

// ---------------- transposes ----------------
__device__ __forceinline__ void tile_tr(float (&sm)[32][33],
    const float* src, int lds, float* dst, int ldd, int tr, int tc)
{
  int x = threadIdx.x & 31, y = threadIdx.x >> 5;
  #pragma unroll
  for (int k=0;k<4;k++)
    sm[y+8*k][x] = src[(long long)(tr*32 + y+8*k)*lds + tc*32 + x];
  __syncthreads();
  #pragma unroll
  for (int k=0;k<4;k++)
    dst[(long long)(tc*32 + y+8*k)*ldd + tr*32 + x] = sm[x][y+8*k];
}

__global__ __launch_bounds__(256) void transpose_g(
    const float* __restrict__ src, int lds, float* __restrict__ dst, int ldd, int ctiles)
{
  __shared__ float sm[32][33];
  int id = blockIdx.x;
  tile_tr(sm, src, lds, dst, ldd, id / ctiles, id % ctiles);
}

__global__ __launch_bounds__(256) void transpose_weights(
    const float* __restrict__ Wq, const float* __restrict__ Wkv,
    const float* __restrict__ We, const float* __restrict__ Wo,
    const float* __restrict__ W1, const float* __restrict__ W2,
    float* __restrict__ wT)
{
  __shared__ float sm[32][33];
  int id = blockIdx.x, l = blockIdx.y;
  float* base = wT + (long long)l*WT_LSTR;
  const float* src; float* dst; int R, C;
  if (id < 128)      {           src = Wq  + (long long)l*131072; dst = base + WT_Q;  R=256;  C=512;  }
  else if (id < 384) { id-=128;  src = Wkv + (long long)l*262144; dst = base + WT_KV; R=256;  C=1024; }
  else if (id < 448) { id-=384;  src = We  + (long long)l*65536;  dst = base + WT_E;  R=128;  C=512;  }
  else if (id < 576) { id-=448;  src = Wo  + (long long)l*131072; dst = base + WT_O;  R=512;  C=256;  }
  else if (id < 832) { id-=576;  src = W1  + (long long)l*262144; dst = base + WT_1;  R=256;  C=1024; }
  else               { id-=832;  src = W2  + (long long)l*262144; dst = base + WT_2;  R=1024; C=256;  }
  int ct = C/32;
  tile_tr(sm, src, C, dst, R, id/ct, id%ct);
}

// ---------------- reductions ----------------
template<int NT>
__device__ __forceinline__ float block_reduce_sum(float v){
  constexpr int NW = NT/32;
  __shared__ float sm[NW];
  #pragma unroll
  for (int o=16;o;o>>=1) v += __shfl_xor_sync(0xffffffffu, v, o);
  if ((threadIdx.x & 31) == 0) sm[threadIdx.x>>5] = v;
  __syncthreads();
  if (threadIdx.x < 32){
    v = (threadIdx.x < NW) ? sm[threadIdx.x] : 0.f;
    #pragma unroll
    for (int o=NW/2;o;o>>=1) v += __shfl_xor_sync(0xffffffffu, v, o);
    if (threadIdx.x == 0) sm[0] = v;
  }
  __syncthreads();
  v = sm[0];
  __syncthreads();
  return v;
}

template<int NT>
__device__ __forceinline__ float block_reduce_max(float v){
  constexpr int NW = NT/32;
  __shared__ float sm[NW];
  #pragma unroll
  for (int o=16;o;o>>=1) v = fmaxf(v, __shfl_xor_sync(0xffffffffu, v, o));
  if ((threadIdx.x & 31) == 0) sm[threadIdx.x>>5] = v;
  __syncthreads();
  if (threadIdx.x < 32){
    v = (threadIdx.x < NW) ? sm[threadIdx.x] : -3.4e38f;
    #pragma unroll
    for (int o=NW/2;o;o>>=1) v = fmaxf(v, __shfl_xor_sync(0xffffffffu, v, o));
    if (threadIdx.x == 0) sm[0] = v;
  }
  __syncthreads();
  v = sm[0];
  __syncthreads();
  return v;
}

// ---------------- LayerNorm over edges: warp per row of 128 ----------------
__global__ __launch_bounds__(256) void ln_edges_kernel(
    const float* __restrict__ e, const float* __restrict__ g,
    const float* __restrict__ b, float* __restrict__ out, int rows)
{
  int wid  = (blockIdx.x * blockDim.x + threadIdx.x) >> 5;
  int lane = threadIdx.x & 31;
  if (wid >= rows) return;
  const float4 v = *(const float4*)(e + (long long)wid*EDGC + lane*4);
  float s  = v.x + v.y + v.z + v.w;
  float s2 = v.x*v.x + v.y*v.y + v.z*v.z + v.w*v.w;
  #pragma unroll
  for (int o=16;o;o>>=1){
    s  += __shfl_xor_sync(0xffffffffu, s,  o);
    s2 += __shfl_xor_sync(0xffffffffu, s2, o);
  }
  float mu   = s * (1.f/128.f);
  float var  = s2 * (1.f/128.f) - mu*mu;
  float rstd = rsqrtf(var + 1e-5f);
  float4 gg = *(const float4*)(g + lane*4);
  float4 bb = *(const float4*)(b + lane*4);
  float4 o4;
  o4.x = (v.x-mu)*rstd*gg.x + bb.x;
  o4.y = (v.y-mu)*rstd*gg.y + bb.y;
  o4.z = (v.z-mu)*rstd*gg.z + bb.z;
  o4.w = (v.w-mu)*rstd*gg.w + bb.w;
  *(float4*)(out + (long long)wid*EDGC + lane*4) = o4;
}

// ---------------- LayerNorm over node rows ----------------
__global__ __launch_bounds__(256) void ln_rows_kernel(
    const float* __restrict__ x, const float* __restrict__ g,
    const float* __restrict__ b, float* __restrict__ y)
{
  int row = blockIdx.x, c = threadIdx.x;
  float v  = x[row*DIMC + c];
  float s  = block_reduce_sum<256>(v);
  float s2 = block_reduce_sum<256>(v*v);
  float mu   = s * (1.f/256.f);
  float var  = s2 * (1.f/256.f) - mu*mu;
  float rstd = rsqrtf(var + 1e-5f);
  y[row*DIMC + c] = (v-mu)*rstd*g[c] + b[c];
}

// ---------------- qe term ----------------
__global__ __launch_bounds__(256) void qe_add_kernel(
    const float* __restrict__ en, const float* __restrict__ u,
    float* __restrict__ sim, float scale)
{
  int b  = blockIdx.x;
  int i  = b / 12;
  int jt = (b % 12) * 32;
  __shared__ float es_t[EDGC][33];
  __shared__ float ut[EDGC][8];
  __shared__ float red[8][32][9];
  int t = threadIdx.x;

  #pragma unroll
  for (int k=0;k<4;k++){
    int idx = t + k*256;
    ut[idx & 127][idx >> 7] = u[i*(NHEAD*EDGC) + idx];
  }
  const float* eb = en + ((long long)i*NND + jt) * EDGC;
  int cl = t & 127;
  #pragma unroll
  for (int k=0;k<16;k++){
    int j = (t >> 7) + (k << 1);
    es_t[cl][j] = eb[(long long)j*EDGC + cl];
  }
  __syncthreads();

  int wpid = t >> 5, lane = t & 31;
  float acc[8] = {};
  int c0 = wpid * 16;
  #pragma unroll
  for (int cc=0; cc<16; cc++){
    int c = c0 + cc;
    float ev = es_t[c][lane];
    float4 u0 = *(const float4*)&ut[c][0];
    float4 u1 = *(const float4*)&ut[c][4];
    acc[0] += ev*u0.x; acc[1] += ev*u0.y; acc[2] += ev*u0.z; acc[3] += ev*u0.w;
    acc[4] += ev*u1.x; acc[5] += ev*u1.y; acc[6] += ev*u1.z; acc[7] += ev*u1.w;
  }
  #pragma unroll
  for (int h=0;h<8;h++) red[wpid][lane][h] = acc[h];
  __syncthreads();

  int h = t >> 5, j = lane;
  float s = 0.f;
  #pragma unroll
  for (int w2=0; w2<8; w2++) s += red[w2][j][h];
  long long o = (long long)h*NN + (long long)i*NND + jt + j;
  sim[o] += scale * s;
}

// ---------------- softmax ----------------
__global__ __launch_bounds__(128) void softmax_kernel(float* __restrict__ sim)
{
  long long row = blockIdx.x;
  float* p = sim + row * NND;
  int t = threadIdx.x;
  float v0 = p[t], v1 = p[t+128], v2 = p[t+256];
  float m = block_reduce_max<128>(fmaxf(v0, fmaxf(v1, v2)));
  float e0 = expf(v0-m), e1 = expf(v1-m), e2 = expf(v2-m);
  float s = block_reduce_sum<128>(e0+e1+e2);
  float inv = 1.f / s;
  p[t] = e0*inv; p[t+128] = e1*inv; p[t+256] = e2*inv;
}

// ---------------- w[i,h,c] = sum_j attn[h,i,j] * edges_n[i,j,c] ----------------
__global__ __launch_bounds__(256) void w_kernel(
    const float* __restrict__ en, const float* __restrict__ attn,
    float* __restrict__ w)
{
  int i = blockIdx.x;
  int c = threadIdx.x & 127;
  int half = threadIdx.x >> 7;
  __shared__ float at[NHEAD][NND];
  __shared__ float red[NHEAD][EDGC];
  for (int idx = threadIdx.x; idx < NHEAD*NND; idx += 256){
    int h = idx / NND, j = idx % NND;
    at[h][j] = attn[(long long)h*NN + (long long)i*NND + j];
  }
  __syncthreads();
  float acc[NHEAD];
  #pragma unroll
  for (int h=0;h<NHEAD;h++) acc[h] = 0.f;
  const float* base = en + (long long)i*NND*EDGC + c;
  #pragma unroll 4
  for (int j = half; j < NND; j += 2){
    float ev = base[(long long)j*EDGC];
    #pragma unroll
    for (int h=0;h<NHEAD;h++) acc[h] += at[h][j] * ev;
  }
  if (half == 1){
    #pragma unroll
    for (int h=0;h<NHEAD;h++) red[h][c] = acc[h];
  }
  __syncthreads();
  if (half == 0){
    #pragma unroll
    for (int h=0;h<NHEAD;h++)
      w[i*(NHEAD*EDGC) + h*EDGC + c] = acc[h] + red[h][c];
  }
}

// ---------------- gated residual ----------------
__global__ __launch_bounds__(256) void gated_kernel(
    const float* __restrict__ out, float* __restrict__ x,
    const float* __restrict__ ga)
{
  int row = blockIdx.x, c = threadIdx.x;
  float o = out[row*DIMC + c];
  float r = x[row*DIMC + c];
  float p = o*ga[c] + r*ga[DIMC + c] + (o-r)*ga[2*DIMC + c];
  float s = block_reduce_sum<256>(p);
  float g = 1.f / (1.f + expf(-s));
  x[row*DIMC + c] = o*g + r*(1.f - g);
}

__global__ void copy_kernel(const float* __restrict__ a, float* __restrict__ b, int n){
  int i = blockIdx.x*256 + threadIdx.x;
  if (i < n) b[i] = a[i];
}

// ---------------- host ----------------
static inline float* symaddr(const void* s){
  void* p = nullptr;
  cudaGetSymbolAddress(&p, s);
  return (float*)p;
}

extern "C" void kernel_launch(void* const* d_in, const int* in_sizes, int n_in,
                              void* d_out, int out_size)
{
  const float* nodes  = (const float*)d_in[0];
  const float* edges  = (const float*)d_in[1];
  // d_in[2] = mask: all-true -> softmax no-op; unused.
  const float* ln_e_g = (const float*)d_in[3];
  const float* ln_e_b = (const float*)d_in[4];
  const float* a_ln_g = (const float*)d_in[5];
  const float* a_ln_b = (const float*)d_in[6];
  const float* Wq     = (const float*)d_in[7];
  const float* bq     = (const float*)d_in[8];
  const float* Wkv    = (const float*)d_in[9];
  const float* bkv    = (const float*)d_in[10];
  const float* We     = (const float*)d_in[11];
  const float* be     = (const float*)d_in[12];
  const float* Wo     = (const float*)d_in[13];
  const float* bo     = (const float*)d_in[14];
  const float* gate_a = (const float*)d_in[15];
  const float* f_ln_g = (const float*)d_in[16];
  const float* f_ln_b = (const float*)d_in[17];
  const float* W1     = (const float*)d_in[18];
  const float* b1     = (const float*)d_in[19];
  const float* W2     = (const float*)d_in[20];
  const float* b2     = (const float*)d_in[21];
  const float* gate_f = (const float*)d_in[22];

  float* out_x   = (float*)d_out;
  float* edges_n = (float*)d_out + NND*DIMC;

  float* x      = symaddr(g_x);
  float* h      = symaddr(g_h);
  float* q      = symaddr(g_q);
  float* kv     = symaddr(g_kv);
  float* vT     = symaddr(g_vT);
  float* u      = symaddr(g_u);
  float* simb   = symaddr(g_sim);
  float* w      = symaddr(g_w);
  float* attout = symaddr(g_attout);
  float* proj   = symaddr(g_proj);
  float* ff     = symaddr(g_ff);
  float* part   = symaddr(g_part);
  float* wT     = symaddr(g_wT);

  const float scale = 0.125f;  // DHEAD^-0.5

  transpose_weights<<<dim3(1088,2), 256>>>(Wq, Wkv, We, Wo, W1, W2, wT);
  ln_edges_kernel<<<NN/8, 256>>>(edges, ln_e_g, ln_e_b, edges_n, NN);
  copy_kernel<<<(NND*DIMC+255)/256, 256>>>(nodes, x, NND*DIMC);

  for (int l = 0; l < 2; l++){
    const float* bq_l  = bq  + l*INNERC;
    const float* bkv_l = bkv + l*2*INNERC;
    const float* We_l  = We  + (long long)l*EDGC*INNERC;
    const float* be_l  = be  + l*INNERC;
    const float* bo_l  = bo  + l*DIMC;
    const float* ga_l  = gate_a + l*3*DIMC;
    const float* gf_l  = gate_f + l*3*DIMC;
    const float* b1_l  = b1  + l*FFC;
    const float* b2_l  = b2  + l*DIMC;
    const float* WqT  = wT + (long long)l*WT_LSTR + WT_Q;   // [512,256]
    const float* WkvT = wT + (long long)l*WT_LSTR + WT_KV;  // [1024,256]
    const float* WeT  = wT + (long long)l*WT_LSTR + WT_E;   // [512,128]
    const float* WoT  = wT + (long long)l*WT_LSTR + WT_O;   // [256,512]
    const float* W1T  = wT + (long long)l*WT_LSTR + WT_1;   // [1024,256]
    const float* W2T  = wT + (long long)l*WT_LSTR + WT_2;   // [256,1024]

    ln_rows_kernel<<<NND, 256>>>(x, a_ln_g + l*DIMC, a_ln_b + l*DIMC, h);

    // q = h@Wq + bq (split4, kper=64)
    gemm_tc<2><<<dim3(8,3,4), 256>>>(INNERC, 64, 4,
        h, DIMC, 0, WqT, DIMC, 0, part, 0, 0, nullptr, 0, 1.f);
    reduce_k<false,false><<<(NND*INNERC/4+255)/256, 256>>>(part, 4, NND, INNERC,
        q, INNERC, 0, bq_l, 0, 1);

    // kv = h@Wkv + bkv (split2, kper=128)
    gemm_tc<2><<<dim3(16,3,2), 256>>>(2*INNERC, 128, 2,
        h, DIMC, 0, WkvT, DIMC, 0, part, 0, 0, nullptr, 0, 1.f);
    reduce_k<false,false><<<(NND*2*INNERC/4+255)/256, 256>>>(part, 2, NND, 2*INNERC,
        kv, 2*INNERC, 0, bkv_l, 0, 1);

    // vT = v^T  ([384,512] -> [512,384])
    transpose_g<<<192, 256>>>(kv + INNERC, 2*INNERC, vT, NND, 16);

    // u[i,h,:] = q[i,h,:] @ We_h^T  (B = We rows, k-major in d)
    gemm_tc<0><<<dim3(2,3,NHEAD), 256>>>(EDGC, DH, 0,
        q, INNERC, DH, We_l, INNERC, DH,
        u, NHEAD*EDGC, EDGC, nullptr, 0, 1.f);

    // sim = scale * q @ k^T
    gemm_tc<0><<<dim3(6,3,NHEAD), 256>>>(NND, DH, 0,
        q, INNERC, DH, kv, 2*INNERC, DH,
        simb, NND, (long long)NN, nullptr, 0, scale);

    qe_add_kernel<<<NND*12, 256>>>(edges_n, u, simb, scale);
    softmax_kernel<<<NHEAD*NND, 128>>>(simb);

    // attout = attn @ v  (B = vT, per-head rows; split4, kper=96)
    gemm_tc<2><<<dim3(1,3,NHEAD*4), 256>>>(DH, 96, 4,
        simb, NND, (long long)NN, vT, NND, (long long)DH*NND,
        part, 0, 0, nullptr, 0, 1.f);
    reduce_k<false,false><<<(NHEAD*NND*DH/4+255)/256, 256>>>(part, 4, NND, DH,
        attout, INNERC, DH, nullptr, 0, NHEAD);

    w_kernel<<<NND, 256>>>(edges_n, simb, w);

    // attout += w @ We_h + be_h  (B = WeT per-head rows; split2, kper=64)
    gemm_tc<2><<<dim3(1,3,NHEAD*2), 256>>>(DH, 64, 2,
        w, NHEAD*EDGC, EDGC, WeT, EDGC, (long long)DH*EDGC,
        part, 0, 0, nullptr, 0, 1.f);
    reduce_k<false,true><<<(NHEAD*NND*DH/4+255)/256, 256>>>(part, 2, NND, DH,
        attout, INNERC, DH, be_l, DH, NHEAD);

    // proj = attout @ Wo + bo (split8, kper=64)
    gemm_tc<2><<<dim3(4,3,8), 256>>>(DIMC, 64, 8,
        attout, INNERC, 0, WoT, INNERC, 0, part, 0, 0, nullptr, 0, 1.f);
    reduce_k<false,false><<<(NND*DIMC/4+255)/256, 256>>>(part, 8, NND, DIMC,
        proj, DIMC, 0, bo_l, 0, 1);

    gated_kernel<<<NND, 256>>>(proj, x, ga_l);

    ln_rows_kernel<<<NND, 256>>>(x, f_ln_g + l*DIMC, f_ln_b + l*DIMC, h);

    // ff = gelu(h@W1 + b1) (split2, kper=128)
    gemm_tc<2><<<dim3(16,3,2), 256>>>(FFC, 128, 2,
        h, DIMC, 0, W1T, DIMC, 0, part, 0, 0, nullptr, 0, 1.f);
    reduce_k<true,false><<<(NND*FFC/4+255)/256, 256>>>(part, 2, NND, FFC,
        ff, FFC, 0, b1_l, 0, 1);

    // proj = ff@W2 + b2 (split8, kper=128)
    gemm_tc<2><<<dim3(4,3,8), 256>>>(DIMC, 128, 8,
        ff, FFC, 0, W2T, FFC, 0, part, 0, 0, nullptr, 0, 1.f);
    reduce_k<false,false><<<(NND*DIMC/4+255)/256, 256>>>(part, 8, NND, DIMC,
        proj, DIMC, 0, b2_l, 0, 1);

    gated_kernel<<<NND, 256>>>(proj, x, gf_l);
  }

  copy_kernel<<<(NND*DIMC+255)/256, 256>>>(x, out_x, NND*DIMC);
}

// round 8
// speedup vs baseline: 1.4088x; 1.4088x over previous
#include <cuda_runtime.h>
#include <math.h>

// Problem constants
#define NND 384          // nodes
#define DIMC 256         // node dim
#define EDGC 128         // edge dim
#define NHEAD 8
#define DH 64
#define INNERC 512
#define FFC 1024
#define NN (NND*NND)

// ---------------- device scratch (static, no allocation) ----------------
__device__ float g_x[NND*DIMC];
__device__ float g_h[NND*DIMC];
__device__ float g_q[NND*INNERC];
__device__ float g_kv[NND*2*INNERC];
__device__ float g_u[NND*NHEAD*EDGC];
__device__ float g_sim[NHEAD*NN];
__device__ float g_w[NND*NHEAD*EDGC];
__device__ float g_attout[NND*INNERC];
__device__ float g_proj[NND*DIMC];
__device__ float g_ff[NND*FFC];
__device__ float g_part[1572864];     // split-K partials (6 MiB)

// ---------------- reductions ----------------
template<int NT>
__device__ __forceinline__ float block_reduce_sum(float v){
  constexpr int NW = NT/32;
  __shared__ float sm[NW];
  #pragma unroll
  for (int o=16;o;o>>=1) v += __shfl_xor_sync(0xffffffffu, v, o);
  if ((threadIdx.x & 31) == 0) sm[threadIdx.x>>5] = v;
  __syncthreads();
  if (threadIdx.x < 32){
    v = (threadIdx.x < NW) ? sm[threadIdx.x] : 0.f;
    #pragma unroll
    for (int o=NW/2;o;o>>=1) v += __shfl_xor_sync(0xffffffffu, v, o);
    if (threadIdx.x == 0) sm[0] = v;
  }
  __syncthreads();
  v = sm[0];
  __syncthreads();
  return v;
}

template<int NT>
__device__ __forceinline__ float2 block_reduce_sum2(float2 v){
  constexpr int NW = NT/32;
  __shared__ float2 sm[NW];
  #pragma unroll
  for (int o=16;o;o>>=1){
    v.x += __shfl_xor_sync(0xffffffffu, v.x, o);
    v.y += __shfl_xor_sync(0xffffffffu, v.y, o);
  }
  if ((threadIdx.x & 31) == 0) sm[threadIdx.x>>5] = v;
  __syncthreads();
  if (threadIdx.x < 32){
    v = (threadIdx.x < NW) ? sm[threadIdx.x] : make_float2(0.f,0.f);
    #pragma unroll
    for (int o=NW/2;o;o>>=1){
      v.x += __shfl_xor_sync(0xffffffffu, v.x, o);
      v.y += __shfl_xor_sync(0xffffffffu, v.y, o);
    }
    if (threadIdx.x == 0) sm[0] = v;
  }
  __syncthreads();
  v = sm[0];
  __syncthreads();
  return v;
}

template<int NT>
__device__ __forceinline__ float block_reduce_max(float v){
  constexpr int NW = NT/32;
  __shared__ float sm[NW];
  #pragma unroll
  for (int o=16;o;o>>=1) v = fmaxf(v, __shfl_xor_sync(0xffffffffu, v, o));
  if ((threadIdx.x & 31) == 0) sm[threadIdx.x>>5] = v;
  __syncthreads();
  if (threadIdx.x < 32){
    v = (threadIdx.x < NW) ? sm[threadIdx.x] : -3.4e38f;
    #pragma unroll
    for (int o=NW/2;o;o>>=1) v = fmaxf(v, __shfl_xor_sync(0xffffffffu, v, o));
    if (threadIdx.x == 0) sm[0] = v;
  }
  __syncthreads();
  v = sm[0];
  __syncthreads();
  return v;
}

// ---------------- GEMM core (64x64 tile, BK=16, 256 thr, 4x4/thr, double-buffered) ----------------
template<bool TB>
__device__ __forceinline__ void gemm_body(
    int K, const float* __restrict__ A, int lda,
    const float* __restrict__ B, int ldb,
    float acc[4][4], int bm, int bn,
    float (&As)[2][16][68], float (&Bs)[2][16][68])
{
  int tid = threadIdx.x;
  int am  = tid >> 2;          // 0..63
  int ak  = (tid & 3) << 2;    // 0,4,8,12
  int bk  = tid >> 4;          // 0..15
  int bn0 = (tid & 15) << 2;   // 0..60
  int tx = tid & 15, ty = tid >> 4;
  int nIter = K >> 4;

  float4 a4 = *(const float4*)(A + (long long)(bm+am)*lda + ak);
  float4 b4 = TB ? *(const float4*)(B + (long long)(bn+am)*ldb + ak)
                 : *(const float4*)(B + (long long)bk*ldb + bn + bn0);
  As[0][ak+0][am]=a4.x; As[0][ak+1][am]=a4.y; As[0][ak+2][am]=a4.z; As[0][ak+3][am]=a4.w;
  if (TB){
    Bs[0][ak+0][am]=b4.x; Bs[0][ak+1][am]=b4.y; Bs[0][ak+2][am]=b4.z; Bs[0][ak+3][am]=b4.w;
  } else {
    *(float4*)&Bs[0][bk][bn0] = b4;
  }

  for (int s = 0; s < nIter; s++){
    __syncthreads();
    int p = s & 1;
    bool more = (s+1 < nIter);
    if (more){
      int k0 = (s+1) << 4;
      a4 = *(const float4*)(A + (long long)(bm+am)*lda + k0 + ak);
      b4 = TB ? *(const float4*)(B + (long long)(bn+am)*ldb + k0 + ak)
              : *(const float4*)(B + (long long)(k0+bk)*ldb + bn + bn0);
    }
    #pragma unroll
    for (int kk=0; kk<16; kk++){
      float4 av = *(const float4*)&As[p][kk][ty<<2];
      float4 bv = *(const float4*)&Bs[p][kk][tx<<2];
      float ar[4] = {av.x, av.y, av.z, av.w};
      float br[4] = {bv.x, bv.y, bv.z, bv.w};
      #pragma unroll
      for (int i=0;i<4;i++)
        #pragma unroll
        for (int j=0;j<4;j++)
          acc[i][j] += ar[i]*br[j];
    }
    if (more){
      int np = p ^ 1;
      As[np][ak+0][am]=a4.x; As[np][ak+1][am]=a4.y; As[np][ak+2][am]=a4.z; As[np][ak+3][am]=a4.w;
      if (TB){
        Bs[np][ak+0][am]=b4.x; Bs[np][ak+1][am]=b4.y; Bs[np][ak+2][am]=b4.z; Bs[np][ak+3][am]=b4.w;
      } else {
        *(float4*)&Bs[np][bk][bn0] = b4;
      }
    }
  }
}

// ---------------- non-split GEMM: C = alpha*A@B(^T) + bias ----------------
template<bool TB>
__global__ __launch_bounds__(256) void gemm_k(
    int M, int N, int K,
    const float* __restrict__ A, int lda, long long sA,
    const float* __restrict__ B, int ldb, long long sB,
    float* __restrict__ C, int ldc, long long sC,
    const float* __restrict__ bias, long long sBias,
    float alpha)
{
  __shared__ float As[2][16][68];
  __shared__ float Bs[2][16][68];
  int z = blockIdx.z;
  A += (long long)z * sA;
  B += (long long)z * sB;
  C += (long long)z * sC;
  if (bias) bias += (long long)z * sBias;
  int bm = blockIdx.y * 64, bn = blockIdx.x * 64;
  float acc[4][4] = {};
  gemm_body<TB>(K, A, lda, B, ldb, acc, bm, bn, As, Bs);
  int tx = threadIdx.x & 15, ty = threadIdx.x >> 4;
  #pragma unroll
  for (int i=0;i<4;i++){
    int m = bm + (ty<<2) + i;
    #pragma unroll
    for (int j=0;j<4;j++){
      int n = bn + (tx<<2) + j;
      float v = alpha * acc[i][j];
      if (bias) v += bias[n];
      C[(long long)m*ldc + n] = v;
    }
  }
}

// ---------------- split-K GEMM: partials -> g_part, deterministic ----------------
template<bool TB>
__global__ __launch_bounds__(256) void gemm_split(
    int M, int N, int nsplit, int kper,
    const float* __restrict__ A, int lda, long long sA,
    const float* __restrict__ B, int ldb, long long sB,
    float* __restrict__ part)
{
  __shared__ float As[2][16][68];
  __shared__ float Bs[2][16][68];
  int z = blockIdx.z;
  int bat = z / nsplit;
  int sp  = z - bat*nsplit;
  A += (long long)bat * sA + (long long)sp * kper;
  B += (long long)bat * sB + (TB ? (long long)sp*kper : (long long)sp*kper*ldb);
  float* C = part + (long long)z * M * N;
  int bm = blockIdx.y * 64, bn = blockIdx.x * 64;
  float acc[4][4] = {};
  gemm_body<TB>(kper, A, lda, B, ldb, acc, bm, bn, As, Bs);
  int tx = threadIdx.x & 15, ty = threadIdx.x >> 4;
  #pragma unroll
  for (int i=0;i<4;i++){
    int m = bm + (ty<<2) + i;
    #pragma unroll
    for (int j=0;j<4;j++){
      int n = bn + (tx<<2) + j;
      C[(long long)m*N + n] = acc[i][j];
    }
  }
}

// ---------------- split-K epilogue reduce: C (+)= sum_s part + bias [GELU] ----------------
template<bool GELU, bool ACCUM>
__global__ __launch_bounds__(256) void reduce_k(
    const float* __restrict__ part, int nsplit, int M, int N,
    float* __restrict__ C, int ldc, long long sC,
    const float* __restrict__ bias, long long sBias, int batch)
{
  int idx = blockIdx.x * 256 + threadIdx.x;
  int per = (M*N) >> 2;
  if (idx >= batch * per) return;
  int b = idx / per;
  int r = idx - b*per;
  int n4c = N >> 2;
  int m = r / n4c;
  int n = (r - m*n4c) << 2;
  long long mn = (long long)M * N;
  const float* p = part + (long long)b*nsplit*mn + (long long)m*N + n;
  float4 s = make_float4(0.f,0.f,0.f,0.f);
  for (int sp = 0; sp < nsplit; sp++){
    float4 v = *(const float4*)(p + (long long)sp*mn);
    s.x += v.x; s.y += v.y; s.z += v.z; s.w += v.w;
  }
  if (bias){
    const float* bb = bias + (long long)b*sBias + n;
    s.x += bb[0]; s.y += bb[1]; s.z += bb[2]; s.w += bb[3];
  }
  float* o = C + (long long)b*sC + (long long)m*ldc + n;
  if (ACCUM){
    float4 c = *(const float4*)o;
    s.x += c.x; s.y += c.y; s.z += c.z; s.w += c.w;
  }
  if (GELU){
    s.x *= normcdff(s.x); s.y *= normcdff(s.y);
    s.z *= normcdff(s.z); s.w *= normcdff(s.w);
  }
  *(float4*)o = s;
}

// ---------------- LayerNorm over edges: warp per row of 128 ----------------
__global__ __launch_bounds__(256) void ln_edges_kernel(
    const float* __restrict__ e, const float* __restrict__ g,
    const float* __restrict__ b, float* __restrict__ out, int rows)
{
  int wid  = (blockIdx.x * blockDim.x + threadIdx.x) >> 5;
  int lane = threadIdx.x & 31;
  if (wid >= rows) return;
  const float4 v = *(const float4*)(e + (long long)wid*EDGC + lane*4);
  float s  = v.x + v.y + v.z + v.w;
  float s2 = v.x*v.x + v.y*v.y + v.z*v.z + v.w*v.w;
  #pragma unroll
  for (int o=16;o;o>>=1){
    s  += __shfl_xor_sync(0xffffffffu, s,  o);
    s2 += __shfl_xor_sync(0xffffffffu, s2, o);
  }
  float mu   = s * (1.f/128.f);
  float var  = s2 * (1.f/128.f) - mu*mu;
  float rstd = rsqrtf(var + 1e-5f);
  float4 gg = *(const float4*)(g + lane*4);
  float4 bb = *(const float4*)(b + lane*4);
  float4 o4;
  o4.x = (v.x-mu)*rstd*gg.x + bb.x;
  o4.y = (v.y-mu)*rstd*gg.y + bb.y;
  o4.z = (v.z-mu)*rstd*gg.z + bb.z;
  o4.w = (v.w-mu)*rstd*gg.w + bb.w;
  *(float4*)(out + (long long)wid*EDGC + lane*4) = o4;
}

// ---------------- init: x = nodes, h = LN(nodes) ----------------
__global__ __launch_bounds__(256) void ln_init_kernel(
    const float* __restrict__ nodes, const float* __restrict__ lg,
    const float* __restrict__ lb, float* __restrict__ x, float* __restrict__ h)
{
  int row = blockIdx.x, c = threadIdx.x;
  float v = nodes[row*DIMC + c];
  x[row*DIMC + c] = v;
  float2 ss = block_reduce_sum2<256>(make_float2(v, v*v));
  float mu   = ss.x * (1.f/256.f);
  float var  = ss.y * (1.f/256.f) - mu*mu;
  float rstd = rsqrtf(var + 1e-5f);
  h[row*DIMC + c] = (v-mu)*rstd*lg[c] + lb[c];
}

// ---------------- fused gated residual (+ optional LN, + optional out copy) ----------------
template<bool DO_LN, bool WRITE_OUT>
__global__ __launch_bounds__(256) void gated_ln_kernel(
    const float* __restrict__ out, float* __restrict__ x,
    const float* __restrict__ ga,
    const float* __restrict__ lg, const float* __restrict__ lb,
    float* __restrict__ h, float* __restrict__ outx)
{
  int row = blockIdx.x, c = threadIdx.x;
  float o = out[row*DIMC + c];
  float r = x[row*DIMC + c];
  float p = o*ga[c] + r*ga[DIMC + c] + (o-r)*ga[2*DIMC + c];
  float s = block_reduce_sum<256>(p);
  float gt = 1.f / (1.f + expf(-s));
  float xn = o*gt + r*(1.f - gt);
  x[row*DIMC + c] = xn;
  if (WRITE_OUT) outx[row*DIMC + c] = xn;
  if (DO_LN){
    float2 ss = block_reduce_sum2<256>(make_float2(xn, xn*xn));
    float mu   = ss.x * (1.f/256.f);
    float var  = ss.y * (1.f/256.f) - mu*mu;
    float rstd = rsqrtf(var + 1e-5f);
    h[row*DIMC + c] = (xn-mu)*rstd*lg[c] + lb[c];
  }
}

// ---------------- qe term: sim[h,i,j] += scale * edges_n[i,j,:]·u[i,h,:] ----------------
__global__ __launch_bounds__(256) void qe_add_kernel(
    const float* __restrict__ en, const float* __restrict__ u,
    float* __restrict__ sim, float scale)
{
  int b  = blockIdx.x;
  int i  = b / 12;
  int jt = (b % 12) * 32;
  __shared__ float es_t[EDGC][33];  // [c][j], conflict-free
  __shared__ float ut[EDGC][8];     // [c][h]
  __shared__ float red[8][32][9];   // [warp][j][h]
  int t = threadIdx.x;

  #pragma unroll
  for (int k=0;k<4;k++){
    int idx = t + k*256;              // idx = h*128 + c
    ut[idx & 127][idx >> 7] = u[i*(NHEAD*EDGC) + idx];
  }
  const float* eb = en + ((long long)i*NND + jt) * EDGC;
  int cl = t & 127;
  #pragma unroll
  for (int k=0;k<16;k++){
    int j = (t >> 7) + (k << 1);
    es_t[cl][j] = eb[(long long)j*EDGC + cl];
  }
  __syncthreads();

  int wpid = t >> 5, lane = t & 31;
  float acc[8] = {};
  int c0 = wpid * 16;
  #pragma unroll
  for (int cc=0; cc<16; cc++){
    int c = c0 + cc;
    float ev = es_t[c][lane];
    float4 u0 = *(const float4*)&ut[c][0];
    float4 u1 = *(const float4*)&ut[c][4];
    acc[0] += ev*u0.x; acc[1] += ev*u0.y; acc[2] += ev*u0.z; acc[3] += ev*u0.w;
    acc[4] += ev*u1.x; acc[5] += ev*u1.y; acc[6] += ev*u1.z; acc[7] += ev*u1.w;
  }
  #pragma unroll
  for (int h=0;h<8;h++) red[wpid][lane][h] = acc[h];
  __syncthreads();

  int h = t >> 5, j = lane;
  float s = 0.f;
  #pragma unroll
  for (int w2=0; w2<8; w2++) s += red[w2][j][h];
  long long o = (long long)h*NN + (long long)i*NND + jt + j;
  sim[o] += scale * s;
}

// ---------------- softmax over j (rows = NHEAD*NND), in place ----------------
__global__ __launch_bounds__(128) void softmax_kernel(float* __restrict__ sim)
{
  long long row = blockIdx.x;
  float* p = sim + row * NND;
  int t = threadIdx.x;
  float v0 = p[t], v1 = p[t+128], v2 = p[t+256];
  float m = block_reduce_max<128>(fmaxf(v0, fmaxf(v1, v2)));
  float e0 = expf(v0-m), e1 = expf(v1-m), e2 = expf(v2-m);
  float s = block_reduce_sum<128>(e0+e1+e2);
  float inv = 1.f / s;
  p[t] = e0*inv; p[t+128] = e1*inv; p[t+256] = e2*inv;
}

// ---------------- w[i,h,c] = sum_j attn[h,i,j] * edges_n[i,j,c] ----------------
__global__ __launch_bounds__(256) void w_kernel(
    const float* __restrict__ en, const float* __restrict__ attn,
    float* __restrict__ w)
{
  int i = blockIdx.x;
  int c = threadIdx.x & 127;
  int half = threadIdx.x >> 7;
  __shared__ float at[NHEAD][NND];
  __shared__ float red[NHEAD][EDGC];
  for (int idx = threadIdx.x; idx < NHEAD*NND; idx += 256){
    int h = idx / NND, j = idx % NND;
    at[h][j] = attn[(long long)h*NN + (long long)i*NND + j];
  }
  __syncthreads();
  float acc[NHEAD];
  #pragma unroll
  for (int h=0;h<NHEAD;h++) acc[h] = 0.f;
  const float* base = en + (long long)i*NND*EDGC + c;
  #pragma unroll 4
  for (int j = half; j < NND; j += 2){
    float ev = base[(long long)j*EDGC];
    #pragma unroll
    for (int h=0;h<NHEAD;h++) acc[h] += at[h][j] * ev;
  }
  if (half == 1){
    #pragma unroll
    for (int h=0;h<NHEAD;h++) red[h][c] = acc[h];
  }
  __syncthreads();
  if (half == 0){
    #pragma unroll
    for (int h=0;h<NHEAD;h++)
      w[i*(NHEAD*EDGC) + h*EDGC + c] = acc[h] + red[h][c];
  }
}

// ---------------- host ----------------
static inline float* symaddr(const void* s){
  void* p = nullptr;
  cudaGetSymbolAddress(&p, s);
  return (float*)p;
}

extern "C" void kernel_launch(void* const* d_in, const int* in_sizes, int n_in,
                              void* d_out, int out_size)
{
  const float* nodes  = (const float*)d_in[0];
  const float* edges  = (const float*)d_in[1];
  // d_in[2] = mask: all-true -> softmax no-op; unused.
  const float* ln_e_g = (const float*)d_in[3];
  const float* ln_e_b = (const float*)d_in[4];
  const float* a_ln_g = (const float*)d_in[5];
  const float* a_ln_b = (const float*)d_in[6];
  const float* Wq     = (const float*)d_in[7];
  const float* bq     = (const float*)d_in[8];
  const float* Wkv    = (const float*)d_in[9];
  const float* bkv    = (const float*)d_in[10];
  const float* We     = (const float*)d_in[11];
  const float* be     = (const float*)d_in[12];
  const float* Wo     = (const float*)d_in[13];
  const float* bo     = (const float*)d_in[14];
  const float* gate_a = (const float*)d_in[15];
  const float* f_ln_g = (const float*)d_in[16];
  const float* f_ln_b = (const float*)d_in[17];
  const float* W1     = (const float*)d_in[18];
  const float* b1     = (const float*)d_in[19];
  const float* W2     = (const float*)d_in[20];
  const float* b2     = (const float*)d_in[21];
  const float* gate_f = (const float*)d_in[22];

  float* out_x   = (float*)d_out;                 // [384,256]
  float* edges_n = (float*)d_out + NND*DIMC;      // [384,384,128]

  float* x      = symaddr(g_x);
  float* h      = symaddr(g_h);
  float* q      = symaddr(g_q);
  float* kv     = symaddr(g_kv);
  float* u      = symaddr(g_u);
  float* simb   = symaddr(g_sim);
  float* w      = symaddr(g_w);
  float* attout = symaddr(g_attout);
  float* proj   = symaddr(g_proj);
  float* ff     = symaddr(g_ff);
  float* part   = symaddr(g_part);

  const float scale = 0.125f;  // DHEAD^-0.5

  ln_edges_kernel<<<NN/8, 256>>>(edges, ln_e_g, ln_e_b, edges_n, NN);
  // x = nodes; h = LN(nodes) with layer-0 attention LN params
  ln_init_kernel<<<NND, 256>>>(nodes, a_ln_g, a_ln_b, x, h);

  for (int l = 0; l < 2; l++){
    const float* Wq_l  = Wq  + (long long)l*DIMC*INNERC;
    const float* bq_l  = bq  + l*INNERC;
    const float* Wkv_l = Wkv + (long long)l*DIMC*2*INNERC;
    const float* bkv_l = bkv + l*2*INNERC;
    const float* We_l  = We  + (long long)l*EDGC*INNERC;
    const float* be_l  = be  + l*INNERC;
    const float* Wo_l  = Wo  + (long long)l*INNERC*DIMC;
    const float* bo_l  = bo  + l*DIMC;
    const float* ga_l  = gate_a + l*3*DIMC;
    const float* gf_l  = gate_f + l*3*DIMC;
    const float* W1_l  = W1  + (long long)l*DIMC*FFC;
    const float* b1_l  = b1  + l*FFC;
    const float* W2_l  = W2  + (long long)l*FFC*DIMC;
    const float* b2_l  = b2  + l*DIMC;

    // q = h@Wq + bq (split4, kper=64 -> 192 blocks)
    gemm_split<false><<<dim3(8,6,4), 256>>>(NND, INNERC, 4, 64,
        h, DIMC, 0, Wq_l, INNERC, 0, part);
    reduce_k<false,false><<<(NND*INNERC/4+255)/256, 256>>>(part, 4, NND, INNERC,
        q, INNERC, 0, bq_l, 0, 1);

    // kv = h@Wkv + bkv (split4, kper=64 -> 384 blocks)
    gemm_split<false><<<dim3(16,6,4), 256>>>(NND, 2*INNERC, 4, 64,
        h, DIMC, 0, Wkv_l, 2*INNERC, 0, part);
    reduce_k<false,false><<<(NND*2*INNERC/4+255)/256, 256>>>(part, 4, NND, 2*INNERC,
        kv, 2*INNERC, 0, bkv_l, 0, 1);

    // u[i,h,:] = q[i,h,:] @ We_h^T (per head, split2, kper=32 -> 192 blocks)
    gemm_split<true><<<dim3(2,6,NHEAD*2), 256>>>(NND, EDGC, 2, 32,
        q, INNERC, DH, We_l, INNERC, DH, part);
    reduce_k<false,false><<<(NHEAD*NND*EDGC/4+255)/256, 256>>>(part, 2, NND, EDGC,
        u, NHEAD*EDGC, EDGC, nullptr, 0, NHEAD);

    // sim = scale * q @ k^T (per head; 288 blocks)
    gemm_k<true><<<dim3(6,6,NHEAD), 256>>>(NND, NND, DH,
        q, INNERC, DH, kv, 2*INNERC, DH, simb, NND, (long long)NN,
        nullptr, 0, scale);

    // sim += scale * edges_n · u
    qe_add_kernel<<<NND*12, 256>>>(edges_n, u, simb, scale);

    // softmax over j
    softmax_kernel<<<NHEAD*NND, 128>>>(simb);

    // attout = attn @ v (per head, split6, kper=64 -> 288 blocks)
    gemm_split<false><<<dim3(1,6,NHEAD*6), 256>>>(NND, DH, 6, 64,
        simb, NND, (long long)NN, kv + INNERC, 2*INNERC, DH, part);
    reduce_k<false,false><<<(NHEAD*NND*DH/4+255)/256, 256>>>(part, 6, NND, DH,
        attout, INNERC, DH, nullptr, 0, NHEAD);

    // w[i,h,:] = attn @ edges_n
    w_kernel<<<NND, 256>>>(edges_n, simb, w);

    // attout += w @ We_h + be_h (per head, split4, kper=32 -> 192 blocks)
    gemm_split<false><<<dim3(1,6,NHEAD*4), 256>>>(NND, DH, 4, 32,
        w, NHEAD*EDGC, EDGC, We_l, INNERC, DH, part);
    reduce_k<false,true><<<(NHEAD*NND*DH/4+255)/256, 256>>>(part, 4, NND, DH,
        attout, INNERC, DH, be_l, DH, NHEAD);

    // proj = attout @ Wo + bo (split8, kper=64 -> 192 blocks)
    gemm_split<false><<<dim3(4,6,8), 256>>>(NND, DIMC, 8, 64,
        attout, INNERC, 0, Wo_l, DIMC, 0, part);
    reduce_k<false,false><<<(NND*DIMC/4+255)/256, 256>>>(part, 8, NND, DIMC,
        proj, DIMC, 0, bo_l, 0, 1);

    // x = gated_residual(proj, x, gate_a); h = LN_f(x)
    gated_ln_kernel<true,false><<<NND, 256>>>(proj, x, ga_l,
        f_ln_g + l*DIMC, f_ln_b + l*DIMC, h, nullptr);

    // ff = gelu(h@W1 + b1) (split4, kper=64 -> 384 blocks)
    gemm_split<false><<<dim3(16,6,4), 256>>>(NND, FFC, 4, 64,
        h, DIMC, 0, W1_l, FFC, 0, part);
    reduce_k<true,false><<<(NND*FFC/4+255)/256, 256>>>(part, 4, NND, FFC,
        ff, FFC, 0, b1_l, 0, 1);

    // proj = ff@W2 + b2 (split16, kper=64 -> 384 blocks)
    gemm_split<false><<<dim3(4,6,16), 256>>>(NND, DIMC, 16, 64,
        ff, FFC, 0, W2_l, DIMC, 0, part);
    reduce_k<false,false><<<(NND*DIMC/4+255)/256, 256>>>(part, 16, NND, DIMC,
        proj, DIMC, 0, b2_l, 0, 1);

    // x = gated_residual(ff_out, x, gate_f); then LN for next layer, or write output
    if (l == 0){
      gated_ln_kernel<true,false><<<NND, 256>>>(proj, x, gf_l,
          a_ln_g + DIMC, a_ln_b + DIMC, h, nullptr);
    } else {
      gated_ln_kernel<false,true><<<NND, 256>>>(proj, x, gf_l,
          nullptr, nullptr, nullptr, out_x);
    }
  }
}